// round 3
// baseline (speedup 1.0000x reference)
#include <cuda_runtime.h>
#include <math.h>

// Problem constants
#define B_ 2
#define S_ 2048
#define E_ 2048
#define H_ 16
#define D_ 128
#define M_ (B_*S_)   // 4096 rows

// ---------------------------------------------------------------------------
// Scratch (no allocations allowed -> __device__ globals)
// ---------------------------------------------------------------------------
__device__ float g_Q[(size_t)M_ * E_];
__device__ float g_K[(size_t)M_ * E_];
__device__ float g_V[(size_t)M_ * E_];
__device__ float g_O[(size_t)M_ * E_];

// ---------------------------------------------------------------------------
// SGEMM: C[M,N] = A[M,K] @ W[N,K]^T   (y = x @ W.T, weights row-major [N,K])
// 128x128 block tile, BK=8, 256 threads, 8x8 per-thread microtile
// ---------------------------------------------------------------------------
#define BM 128
#define BN 128
#define BK 8

__device__ __forceinline__ void sgemm_body(const float* __restrict__ A,
                                           const float* __restrict__ W,
                                           float* __restrict__ C,
                                           int K, int N) {
    __shared__ float As[BK][BM];
    __shared__ float Ws[BK][BN];

    const int tid = threadIdx.x;
    const int tx  = tid & 15;       // 0..15 -> N direction
    const int ty  = tid >> 4;       // 0..15 -> M direction
    const int row0 = blockIdx.y * BM;
    const int col0 = blockIdx.x * BN;

    // cooperative load indices: 256 threads x float4 = 1024 floats per tile
    const int lr = tid >> 1;        // 0..127 (row within tile)
    const int lc = (tid & 1) * 4;   // 0 or 4 (k within tile)

    const float* Ag = A + (size_t)(row0 + lr) * K + lc;
    const float* Wg = W + (size_t)(col0 + lr) * K + lc;

    float acc[8][8];
#pragma unroll
    for (int i = 0; i < 8; i++)
#pragma unroll
        for (int j = 0; j < 8; j++) acc[i][j] = 0.0f;

    for (int k0 = 0; k0 < K; k0 += BK) {
        float4 a4 = *(const float4*)(Ag + k0);
        float4 w4 = *(const float4*)(Wg + k0);
        As[lc + 0][lr] = a4.x; As[lc + 1][lr] = a4.y;
        As[lc + 2][lr] = a4.z; As[lc + 3][lr] = a4.w;
        Ws[lc + 0][lr] = w4.x; Ws[lc + 1][lr] = w4.y;
        Ws[lc + 2][lr] = w4.z; Ws[lc + 3][lr] = w4.w;
        __syncthreads();

#pragma unroll
        for (int kk = 0; kk < BK; kk++) {
            float ra[8], rb[8];
            *(float4*)&ra[0] = *(const float4*)&As[kk][ty * 8];
            *(float4*)&ra[4] = *(const float4*)&As[kk][ty * 8 + 4];
            *(float4*)&rb[0] = *(const float4*)&Ws[kk][tx * 8];
            *(float4*)&rb[4] = *(const float4*)&Ws[kk][tx * 8 + 4];
#pragma unroll
            for (int i = 0; i < 8; i++)
#pragma unroll
                for (int j = 0; j < 8; j++)
                    acc[i][j] += ra[i] * rb[j];
        }
        __syncthreads();
    }

#pragma unroll
    for (int i = 0; i < 8; i++) {
        float* Cr = C + (size_t)(row0 + ty * 8 + i) * N + col0 + tx * 8;
        *(float4*)(Cr)     = make_float4(acc[i][0], acc[i][1], acc[i][2], acc[i][3]);
        *(float4*)(Cr + 4) = make_float4(acc[i][4], acc[i][5], acc[i][6], acc[i][7]);
    }
}

// fused QKV: blockIdx.z selects weight + destination
__global__ __launch_bounds__(256, 2)
void sgemm_qkv(const float* __restrict__ x,
               const float* __restrict__ Wq,
               const float* __restrict__ Wk,
               const float* __restrict__ Wv) {
    const float* W = (blockIdx.z == 0) ? Wq : ((blockIdx.z == 1) ? Wk : Wv);
    float* C       = (blockIdx.z == 0) ? g_Q : ((blockIdx.z == 1) ? g_K : g_V);
    sgemm_body(x, W, C, E_, E_);
}

__global__ __launch_bounds__(256, 2)
void sgemm_out(const float* __restrict__ Wo, float* __restrict__ out) {
    sgemm_body(g_O, Wo, out, E_, E_);
}

// ---------------------------------------------------------------------------
// Flash attention (causal), fp32.
// Block: 256 threads, 64 queries x 64 keys tiles, D=128.
// Thread grid 16x16: score phase thread (ty,tx) owns rows ty*4..+3,
// cols {tx, tx+16, tx+32, tx+48}; PV/output phase owns same rows,
// cols tx*8..tx*8+7 (P goes through smem so remaps are safe).
// ---------------------------------------------------------------------------
#define AQ  64
#define AKV 64
#define QST 132     // padded row stride (floats) for Q/K/V tiles
#define PST 68      // padded row stride for P tile
#define ATT_SMEM_FLOATS (AQ*QST + AKV*QST + AQ*PST)
#define ATT_SMEM_BYTES  (ATT_SMEM_FLOATS * 4)

__global__ __launch_bounds__(256, 2)
void flash_attn() {
    extern __shared__ float sm[];
    float* Qs  = sm;                        // [AQ][QST]
    float* KVs = sm + AQ * QST;             // [AKV][QST], shared by K then V
    float* Ps  = sm + AQ * QST + AKV * QST; // [AQ][PST]

    const int tid = threadIdx.x;
    const int tx  = tid & 15;
    const int ty  = tid >> 4;
    const int bh  = blockIdx.y;
    const int b   = bh >> 4;
    const int h   = bh & 15;
    const int q0  = blockIdx.x * AQ;

    const float scale = 0.08838834764831845f;   // 1/sqrt(128)
    const size_t base = (size_t)b * S_ * E_ + (size_t)h * D_;

    // load + pre-scale Q tile
    for (int i = tid; i < AQ * (D_ / 4); i += 256) {
        int r  = i >> 5;           // D_/4 = 32 float4 per row
        int d4 = (i & 31) << 2;
        float4 v = *(const float4*)(g_Q + base + (size_t)(q0 + r) * E_ + d4);
        float* q = Qs + r * QST + d4;
        q[0] = v.x * scale; q[1] = v.y * scale;
        q[2] = v.z * scale; q[3] = v.w * scale;
    }

    float m_i[4], l_i[4], acc[4][8];
#pragma unroll
    for (int i = 0; i < 4; i++) {
        m_i[i] = -1e30f;
        l_i[i] = 0.0f;
#pragma unroll
        for (int j = 0; j < 8; j++) acc[i][j] = 0.0f;
    }

    const int nkt = q0 / AKV + 1;   // causal: key tiles 0..q0/AKV
    for (int kt = 0; kt < nkt; kt++) {
        const int k0 = kt * AKV;

        __syncthreads();   // protects KVs reuse (and orders Q load on kt==0)
        // load K tile
        for (int i = tid; i < AKV * (D_ / 4); i += 256) {
            int r  = i >> 5;
            int d4 = (i & 31) << 2;
            float4 v = *(const float4*)(g_K + base + (size_t)(k0 + r) * E_ + d4);
            float* p = KVs + r * QST + d4;
            p[0] = v.x; p[1] = v.y; p[2] = v.z; p[3] = v.w;
        }
        __syncthreads();

        // scores S = Qs . K^T  (Q already scaled)
        float s[4][4];
#pragma unroll
        for (int i = 0; i < 4; i++)
#pragma unroll
            for (int j = 0; j < 4; j++) s[i][j] = 0.0f;

        for (int d = 0; d < D_; d += 4) {
            float4 qf[4], kf[4];
#pragma unroll
            for (int i = 0; i < 4; i++)
                qf[i] = *(const float4*)(Qs + (ty * 4 + i) * QST + d);
#pragma unroll
            for (int j = 0; j < 4; j++)
                kf[j] = *(const float4*)(KVs + (tx + 16 * j) * QST + d);
#pragma unroll
            for (int i = 0; i < 4; i++)
#pragma unroll
                for (int j = 0; j < 4; j++) {
                    s[i][j] += qf[i].x * kf[j].x;
                    s[i][j] += qf[i].y * kf[j].y;
                    s[i][j] += qf[i].z * kf[j].z;
                    s[i][j] += qf[i].w * kf[j].w;
                }
        }

        // causal mask: only the diagonal tile needs it
        if (k0 + AKV > q0) {
#pragma unroll
            for (int i = 0; i < 4; i++) {
                int qg = q0 + ty * 4 + i;
#pragma unroll
                for (int j = 0; j < 4; j++) {
                    int kg = k0 + tx + 16 * j;
                    if (kg > qg) s[i][j] = -1e9f;
                }
            }
        }

        // online softmax update (per row, replicated across the 16 tx lanes)
#pragma unroll
        for (int i = 0; i < 4; i++) {
            float rm = fmaxf(fmaxf(s[i][0], s[i][1]), fmaxf(s[i][2], s[i][3]));
            rm = fmaxf(rm, __shfl_xor_sync(0xffffffffu, rm, 1));
            rm = fmaxf(rm, __shfl_xor_sync(0xffffffffu, rm, 2));
            rm = fmaxf(rm, __shfl_xor_sync(0xffffffffu, rm, 4));
            rm = fmaxf(rm, __shfl_xor_sync(0xffffffffu, rm, 8));
            float mnew = fmaxf(m_i[i], rm);
            float corr = __expf(m_i[i] - mnew);
            m_i[i] = mnew;
            float p0 = __expf(s[i][0] - mnew);
            float p1 = __expf(s[i][1] - mnew);
            float p2 = __expf(s[i][2] - mnew);
            float p3 = __expf(s[i][3] - mnew);
            float rs = p0 + p1 + p2 + p3;
            rs += __shfl_xor_sync(0xffffffffu, rs, 1);
            rs += __shfl_xor_sync(0xffffffffu, rs, 2);
            rs += __shfl_xor_sync(0xffffffffu, rs, 4);
            rs += __shfl_xor_sync(0xffffffffu, rs, 8);
            l_i[i] = l_i[i] * corr + rs;
#pragma unroll
            for (int jj = 0; jj < 8; jj++) acc[i][jj] *= corr;
            float* pr = Ps + (ty * 4 + i) * PST + tx;
            pr[0]  = p0;
            pr[16] = p1;
            pr[32] = p2;
            pr[48] = p3;
        }
        __syncthreads();   // Ps visible; K reads done -> reuse KVs for V

        // load V tile
        for (int i = tid; i < AKV * (D_ / 4); i += 256) {
            int r  = i >> 5;
            int d4 = (i & 31) << 2;
            float4 v = *(const float4*)(g_V + base + (size_t)(k0 + r) * E_ + d4);
            float* p = KVs + r * QST + d4;
            p[0] = v.x; p[1] = v.y; p[2] = v.z; p[3] = v.w;
        }
        __syncthreads();

        // O += P . V  (thread owns rows ty*4..+3, cols tx*8..+7)
        for (int k = 0; k < AKV; k++) {
            float4 va = *(const float4*)(KVs + k * QST + tx * 8);
            float4 vb = *(const float4*)(KVs + k * QST + tx * 8 + 4);
            float pr[4];
#pragma unroll
            for (int i = 0; i < 4; i++)
                pr[i] = Ps[(ty * 4 + i) * PST + k];
#pragma unroll
            for (int i = 0; i < 4; i++) {
                acc[i][0] += pr[i] * va.x;
                acc[i][1] += pr[i] * va.y;
                acc[i][2] += pr[i] * va.z;
                acc[i][3] += pr[i] * va.w;
                acc[i][4] += pr[i] * vb.x;
                acc[i][5] += pr[i] * vb.y;
                acc[i][6] += pr[i] * vb.z;
                acc[i][7] += pr[i] * vb.w;
            }
        }
    }

    // epilogue: normalize + write head slice into g_O (concat layout)
#pragma unroll
    for (int i = 0; i < 4; i++) {
        float inv = 1.0f / l_i[i];
        float* o = g_O + base + (size_t)(q0 + ty * 4 + i) * E_ + tx * 8;
        *(float4*)(o)     = make_float4(acc[i][0] * inv, acc[i][1] * inv,
                                        acc[i][2] * inv, acc[i][3] * inv);
        *(float4*)(o + 4) = make_float4(acc[i][4] * inv, acc[i][5] * inv,
                                        acc[i][6] * inv, acc[i][7] * inv);
    }
}

// ---------------------------------------------------------------------------
// Launch
// ---------------------------------------------------------------------------
extern "C" void kernel_launch(void* const* d_in, const int* in_sizes, int n_in,
                              void* d_out, int out_size) {
    (void)in_sizes; (void)n_in; (void)out_size;
    const float* x  = (const float*)d_in[0];
    const float* Wq = (const float*)d_in[1];
    const float* Wk = (const float*)d_in[2];
    const float* Wv = (const float*)d_in[3];
    const float* Wo = (const float*)d_in[4];
    float* out = (float*)d_out;

    // opt-in to >48KB dynamic smem for the attention kernel (idempotent,
    // not a stream op -> safe under graph capture)
    cudaFuncSetAttribute(flash_attn, cudaFuncAttributeMaxDynamicSharedMemorySize,
                         ATT_SMEM_BYTES);

    dim3 gqkv(E_ / BN, M_ / BM, 3);
    sgemm_qkv<<<gqkv, 256>>>(x, Wq, Wk, Wv);

    dim3 gatt(S_ / AQ, B_ * H_);
    flash_attn<<<gatt, 256, ATT_SMEM_BYTES>>>();

    dim3 gout(E_ / BN, M_ / BM);
    sgemm_out<<<gout, 256>>>(Wo, out);
}

// round 5
// speedup vs baseline: 1.5891x; 1.5891x over previous
#include <cuda_runtime.h>
#include <math.h>
#include <stdint.h>

// Problem constants
#define B_ 2
#define S_ 2048
#define E_ 2048
#define H_ 16
#define D_ 128
#define M_ (B_*S_)   // 4096 rows

// ---------------------------------------------------------------------------
// Scratch (no allocations allowed -> __device__ globals)
// ---------------------------------------------------------------------------
__device__ float g_Q[(size_t)M_ * E_];
__device__ float g_K[(size_t)M_ * E_];
__device__ float g_V[(size_t)M_ * E_];
__device__ float g_O[(size_t)M_ * E_];

// ===========================================================================
// Warp-level helpers (base sm_103 ISA only: ldmatrix + mma.sync, NO tcgen05)
// ===========================================================================
__device__ __forceinline__ uint32_t smem_u32(const void* p) {
    uint32_t a;
    asm("{ .reg .u64 t; cvta.to.shared.u64 t, %1; cvt.u32.u64 %0, t; }"
        : "=r"(a) : "l"(p));
    return a;
}

__device__ __forceinline__ void ldsm4(uint32_t* r, uint32_t addr) {
    asm volatile("ldmatrix.sync.aligned.m8n8.x4.shared.b16 {%0,%1,%2,%3}, [%4];"
                 : "=r"(r[0]), "=r"(r[1]), "=r"(r[2]), "=r"(r[3]) : "r"(addr));
}

__device__ __forceinline__ void mma_bf16(float* c, const uint32_t* a,
                                         const uint32_t* b) {
    asm volatile(
        "mma.sync.aligned.m16n8k16.row.col.f32.bf16.bf16.f32 "
        "{%0,%1,%2,%3}, {%4,%5,%6,%7}, {%8,%9}, {%0,%1,%2,%3};"
        : "+f"(c[0]), "+f"(c[1]), "+f"(c[2]), "+f"(c[3])
        : "r"(a[0]), "r"(a[1]), "r"(a[2]), "r"(a[3]), "r"(b[0]), "r"(b[1]));
}

// fp32 -> bf16(hi) + bf16(lo), round-to-nearest-even, manual (data is finite)
__device__ __forceinline__ void bsplit(float x, uint32_t& h16, uint32_t& l16) {
    uint32_t u = __float_as_uint(x);
    h16 = (u + 0x7fffu + ((u >> 16) & 1u)) >> 16;
    float hf = __uint_as_float(h16 << 16);
    float lf = x - hf;
    uint32_t v = __float_as_uint(lf);
    l16 = (v + 0x7fffu + ((v >> 16) & 1u)) >> 16;
}

// pack two (hi,lo) splits of consecutive-k floats into hi-word / lo-word
__device__ __forceinline__ void bpack2(float e, float o, uint32_t& hw, uint32_t& lw) {
    uint32_t he, le, ho, lo;
    bsplit(e, he, le);
    bsplit(o, ho, lo);
    hw = he | (ho << 16);
    lw = le | (lo << 16);
}

// ===========================================================================
// bf16 mma.sync GEMM with 3-pass error compensation:
//   C[M,N] = A[M,K] @ W[N,K]^T
// 128x128 block tile, k-chunk 32, 256 threads (8 warps of 64x32).
// SMEM tiles: rows of 32 bf16 (64B) + 16B pad -> 80B stride, conflict-free
// ldmatrix. Tiles: Ah, Al, Wh, Wl (10240 B each).
// ===========================================================================
#define GK 32
#define NCHUNK (E_ / GK)        // 64
#define TROW 80                 // bytes per smem tile row
#define TILEB (128 * TROW)      // 10240
#define GEMM_SMEM (4 * TILEB)   // 40960

__device__ __forceinline__ void gemm_mma_body(const float* __restrict__ A,
                                              const float* __restrict__ W,
                                              float* __restrict__ C) {
    extern __shared__ char dsm[];
    const uint32_t sAh = smem_u32(dsm);
    const uint32_t sAl = sAh + TILEB;
    const uint32_t sWh = sAh + 2 * TILEB;
    const uint32_t sWl = sAh + 3 * TILEB;

    const int tid  = threadIdx.x;
    const int lane = tid & 31;
    const int wid  = tid >> 5;
    const int wm   = (wid & 1) * 64;    // warp m-offset within tile
    const int wn   = (wid >> 1) * 32;   // warp n-offset within tile
    const int row0 = blockIdx.y * 128;
    const int col0 = blockIdx.x * 128;

    // ldmatrix lane-address components
    const int lr8 = lane & 7;
    const uint32_t aBase = (uint32_t)((wm + lr8 + 8 * ((lane >> 3) & 1)) * TROW
                                      + (lane >> 4) * 16);
    const uint32_t bBase = (uint32_t)((wn + lr8 + 8 * (lane >> 4)) * TROW
                                      + ((lane >> 3) & 1) * 16);

    // global load mapping: thread -> row tid/2, k-offset (tid&1)*16
    const int glr = tid >> 1;
    const int gkq = (tid & 1) * 16;
    const float* Ag = A + (size_t)(row0 + glr) * E_ + gkq;
    const float* Wg = W + (size_t)(col0 + glr) * E_ + gkq;
    const uint32_t stOff = (uint32_t)(glr * TROW + (gkq >> 3) * 16);

    float acc[4][4][4];
#pragma unroll
    for (int i = 0; i < 4; i++)
#pragma unroll
        for (int j = 0; j < 4; j++)
#pragma unroll
            for (int q = 0; q < 4; q++) acc[i][j][q] = 0.0f;

    // prefetch chunk 0
    float4 rA[4], rW[4];
#pragma unroll
    for (int j = 0; j < 4; j++) {
        rA[j] = *(const float4*)(Ag + j * 4);
        rW[j] = *(const float4*)(Wg + j * 4);
    }

    for (int c = 0; c < NCHUNK; ++c) {
        __syncthreads();    // previous chunk's compute done -> safe to overwrite
        // convert + store this thread's 16 A floats and 16 W floats
        {
            uint4 h0, l0, h1, l1;
            bpack2(rA[0].x, rA[0].y, h0.x, l0.x);
            bpack2(rA[0].z, rA[0].w, h0.y, l0.y);
            bpack2(rA[1].x, rA[1].y, h0.z, l0.z);
            bpack2(rA[1].z, rA[1].w, h0.w, l0.w);
            bpack2(rA[2].x, rA[2].y, h1.x, l1.x);
            bpack2(rA[2].z, rA[2].w, h1.y, l1.y);
            bpack2(rA[3].x, rA[3].y, h1.z, l1.z);
            bpack2(rA[3].z, rA[3].w, h1.w, l1.w);
            *(uint4*)(dsm + (sAh - sAh) + stOff)           = h0;  // Ah chunk0
            *(uint4*)(dsm + (sAh - sAh) + stOff + 16)      = h1;  // Ah chunk1
            *(uint4*)(dsm + TILEB + stOff)                 = l0;  // Al
            *(uint4*)(dsm + TILEB + stOff + 16)            = l1;
            bpack2(rW[0].x, rW[0].y, h0.x, l0.x);
            bpack2(rW[0].z, rW[0].w, h0.y, l0.y);
            bpack2(rW[1].x, rW[1].y, h0.z, l0.z);
            bpack2(rW[1].z, rW[1].w, h0.w, l0.w);
            bpack2(rW[2].x, rW[2].y, h1.x, l1.x);
            bpack2(rW[2].z, rW[2].w, h1.y, l1.y);
            bpack2(rW[3].x, rW[3].y, h1.z, l1.z);
            bpack2(rW[3].z, rW[3].w, h1.w, l1.w);
            *(uint4*)(dsm + 2 * TILEB + stOff)             = h0;  // Wh
            *(uint4*)(dsm + 2 * TILEB + stOff + 16)        = h1;
            *(uint4*)(dsm + 3 * TILEB + stOff)             = l0;  // Wl
            *(uint4*)(dsm + 3 * TILEB + stOff + 16)        = l1;
        }
        __syncthreads();

        // prefetch next chunk (latency overlapped with mma below)
        if (c + 1 < NCHUNK) {
            const float* An = Ag + (c + 1) * GK;
            const float* Wn = Wg + (c + 1) * GK;
#pragma unroll
            for (int j = 0; j < 4; j++) {
                rA[j] = *(const float4*)(An + j * 4);
                rW[j] = *(const float4*)(Wn + j * 4);
            }
        }

        // compute: 2 x k16 steps
#pragma unroll
        for (int kk = 0; kk < 2; ++kk) {
            uint32_t ah[4][4], al[4][4];
#pragma unroll
            for (int mf = 0; mf < 4; mf++) {
                ldsm4(ah[mf], sAh + aBase + (uint32_t)(mf * 16 * TROW + kk * 32));
                ldsm4(al[mf], sAl + aBase + (uint32_t)(mf * 16 * TROW + kk * 32));
            }
            uint32_t bh[2][4], bl[2][4];
#pragma unroll
            for (int p = 0; p < 2; p++) {
                ldsm4(bh[p], sWh + bBase + (uint32_t)(p * 16 * TROW + kk * 32));
                ldsm4(bl[p], sWl + bBase + (uint32_t)(p * 16 * TROW + kk * 32));
            }
#pragma unroll
            for (int p = 0; p < 2; p++)
#pragma unroll
                for (int q = 0; q < 2; q++) {
                    const int nf = p * 2 + q;
#pragma unroll
                    for (int mf = 0; mf < 4; mf++) {
                        mma_bf16(acc[mf][nf], ah[mf], &bh[p][q * 2]);
                        mma_bf16(acc[mf][nf], ah[mf], &bl[p][q * 2]);
                        mma_bf16(acc[mf][nf], al[mf], &bh[p][q * 2]);
                    }
                }
        }
    }

    // epilogue: write accumulators
    const int cr = lane >> 2;          // 0..7
    const int cc = (lane & 3) * 2;     // 0,2,4,6
#pragma unroll
    for (int mf = 0; mf < 4; mf++) {
#pragma unroll
        for (int nf = 0; nf < 4; nf++) {
            float* p0 = C + (size_t)(row0 + wm + mf * 16 + cr) * E_
                          + col0 + wn + nf * 8 + cc;
            float* p1 = p0 + 8 * E_;
            *(float2*)p0 = make_float2(acc[mf][nf][0], acc[mf][nf][1]);
            *(float2*)p1 = make_float2(acc[mf][nf][2], acc[mf][nf][3]);
        }
    }
}

__global__ __launch_bounds__(256, 1)
void gemm_qkv_mma(const float* __restrict__ x,
                  const float* __restrict__ Wq,
                  const float* __restrict__ Wk,
                  const float* __restrict__ Wv) {
    const float* W = (blockIdx.z == 0) ? Wq : ((blockIdx.z == 1) ? Wk : Wv);
    float* C       = (blockIdx.z == 0) ? g_Q : ((blockIdx.z == 1) ? g_K : g_V);
    gemm_mma_body(x, W, C);
}

__global__ __launch_bounds__(256, 1)
void gemm_out_mma(const float* __restrict__ Wo, float* __restrict__ out) {
    gemm_mma_body(g_O, Wo, out);
}

// ---------------------------------------------------------------------------
// Flash attention (causal), fp32 — unchanged from R3 (passing baseline).
// ---------------------------------------------------------------------------
#define AQ  64
#define AKV 64
#define QST 132     // padded row stride (floats) for Q/K/V tiles
#define PST 68      // padded row stride for P tile
#define ATT_SMEM_FLOATS (AQ*QST + AKV*QST + AQ*PST)
#define ATT_SMEM_BYTES  (ATT_SMEM_FLOATS * 4)

__global__ __launch_bounds__(256, 2)
void flash_attn() {
    extern __shared__ float sm[];
    float* Qs  = sm;                        // [AQ][QST]
    float* KVs = sm + AQ * QST;             // [AKV][QST], shared by K then V
    float* Ps  = sm + AQ * QST + AKV * QST; // [AQ][PST]

    const int tid = threadIdx.x;
    const int tx  = tid & 15;
    const int ty  = tid >> 4;
    const int bh  = blockIdx.y;
    const int b   = bh >> 4;
    const int h   = bh & 15;
    const int q0  = blockIdx.x * AQ;

    const float scale = 0.08838834764831845f;   // 1/sqrt(128)
    const size_t base = (size_t)b * S_ * E_ + (size_t)h * D_;

    // load + pre-scale Q tile
    for (int i = tid; i < AQ * (D_ / 4); i += 256) {
        int r  = i >> 5;           // D_/4 = 32 float4 per row
        int d4 = (i & 31) << 2;
        float4 v = *(const float4*)(g_Q + base + (size_t)(q0 + r) * E_ + d4);
        float* q = Qs + r * QST + d4;
        q[0] = v.x * scale; q[1] = v.y * scale;
        q[2] = v.z * scale; q[3] = v.w * scale;
    }

    float m_i[4], l_i[4], acc[4][8];
#pragma unroll
    for (int i = 0; i < 4; i++) {
        m_i[i] = -1e30f;
        l_i[i] = 0.0f;
#pragma unroll
        for (int j = 0; j < 8; j++) acc[i][j] = 0.0f;
    }

    const int nkt = q0 / AKV + 1;   // causal: key tiles 0..q0/AKV
    for (int kt = 0; kt < nkt; kt++) {
        const int k0 = kt * AKV;

        __syncthreads();   // protects KVs reuse (and orders Q load on kt==0)
        // load K tile
        for (int i = tid; i < AKV * (D_ / 4); i += 256) {
            int r  = i >> 5;
            int d4 = (i & 31) << 2;
            float4 v = *(const float4*)(g_K + base + (size_t)(k0 + r) * E_ + d4);
            float* p = KVs + r * QST + d4;
            p[0] = v.x; p[1] = v.y; p[2] = v.z; p[3] = v.w;
        }
        __syncthreads();

        // scores S = Qs . K^T  (Q already scaled)
        float s[4][4];
#pragma unroll
        for (int i = 0; i < 4; i++)
#pragma unroll
            for (int j = 0; j < 4; j++) s[i][j] = 0.0f;

        for (int d = 0; d < D_; d += 4) {
            float4 qf[4], kf[4];
#pragma unroll
            for (int i = 0; i < 4; i++)
                qf[i] = *(const float4*)(Qs + (ty * 4 + i) * QST + d);
#pragma unroll
            for (int j = 0; j < 4; j++)
                kf[j] = *(const float4*)(KVs + (tx + 16 * j) * QST + d);
#pragma unroll
            for (int i = 0; i < 4; i++)
#pragma unroll
                for (int j = 0; j < 4; j++) {
                    s[i][j] += qf[i].x * kf[j].x;
                    s[i][j] += qf[i].y * kf[j].y;
                    s[i][j] += qf[i].z * kf[j].z;
                    s[i][j] += qf[i].w * kf[j].w;
                }
        }

        // causal mask: only the diagonal tile needs it
        if (k0 + AKV > q0) {
#pragma unroll
            for (int i = 0; i < 4; i++) {
                int qg = q0 + ty * 4 + i;
#pragma unroll
                for (int j = 0; j < 4; j++) {
                    int kg = k0 + tx + 16 * j;
                    if (kg > qg) s[i][j] = -1e9f;
                }
            }
        }

        // online softmax update (per row, replicated across the 16 tx lanes)
#pragma unroll
        for (int i = 0; i < 4; i++) {
            float rm = fmaxf(fmaxf(s[i][0], s[i][1]), fmaxf(s[i][2], s[i][3]));
            rm = fmaxf(rm, __shfl_xor_sync(0xffffffffu, rm, 1));
            rm = fmaxf(rm, __shfl_xor_sync(0xffffffffu, rm, 2));
            rm = fmaxf(rm, __shfl_xor_sync(0xffffffffu, rm, 4));
            rm = fmaxf(rm, __shfl_xor_sync(0xffffffffu, rm, 8));
            float mnew = fmaxf(m_i[i], rm);
            float corr = __expf(m_i[i] - mnew);
            m_i[i] = mnew;
            float p0 = __expf(s[i][0] - mnew);
            float p1 = __expf(s[i][1] - mnew);
            float p2 = __expf(s[i][2] - mnew);
            float p3 = __expf(s[i][3] - mnew);
            float rs = p0 + p1 + p2 + p3;
            rs += __shfl_xor_sync(0xffffffffu, rs, 1);
            rs += __shfl_xor_sync(0xffffffffu, rs, 2);
            rs += __shfl_xor_sync(0xffffffffu, rs, 4);
            rs += __shfl_xor_sync(0xffffffffu, rs, 8);
            l_i[i] = l_i[i] * corr + rs;
#pragma unroll
            for (int jj = 0; jj < 8; jj++) acc[i][jj] *= corr;
            float* pr = Ps + (ty * 4 + i) * PST + tx;
            pr[0]  = p0;
            pr[16] = p1;
            pr[32] = p2;
            pr[48] = p3;
        }
        __syncthreads();   // Ps visible; K reads done -> reuse KVs for V

        // load V tile
        for (int i = tid; i < AKV * (D_ / 4); i += 256) {
            int r  = i >> 5;
            int d4 = (i & 31) << 2;
            float4 v = *(const float4*)(g_V + base + (size_t)(k0 + r) * E_ + d4);
            float* p = KVs + r * QST + d4;
            p[0] = v.x; p[1] = v.y; p[2] = v.z; p[3] = v.w;
        }
        __syncthreads();

        // O += P . V  (thread owns rows ty*4..+3, cols tx*8..+7)
        for (int k = 0; k < AKV; k++) {
            float4 va = *(const float4*)(KVs + k * QST + tx * 8);
            float4 vb = *(const float4*)(KVs + k * QST + tx * 8 + 4);
            float pr[4];
#pragma unroll
            for (int i = 0; i < 4; i++)
                pr[i] = Ps[(ty * 4 + i) * PST + k];
#pragma unroll
            for (int i = 0; i < 4; i++) {
                acc[i][0] += pr[i] * va.x;
                acc[i][1] += pr[i] * va.y;
                acc[i][2] += pr[i] * va.z;
                acc[i][3] += pr[i] * va.w;
                acc[i][4] += pr[i] * vb.x;
                acc[i][5] += pr[i] * vb.y;
                acc[i][6] += pr[i] * vb.z;
                acc[i][7] += pr[i] * vb.w;
            }
        }
    }

    // epilogue: normalize + write head slice into g_O (concat layout)
#pragma unroll
    for (int i = 0; i < 4; i++) {
        float inv = 1.0f / l_i[i];
        float* o = g_O + base + (size_t)(q0 + ty * 4 + i) * E_ + tx * 8;
        *(float4*)(o)     = make_float4(acc[i][0] * inv, acc[i][1] * inv,
                                        acc[i][2] * inv, acc[i][3] * inv);
        *(float4*)(o + 4) = make_float4(acc[i][4] * inv, acc[i][5] * inv,
                                        acc[i][6] * inv, acc[i][7] * inv);
    }
}

// ---------------------------------------------------------------------------
// Launch
// ---------------------------------------------------------------------------
extern "C" void kernel_launch(void* const* d_in, const int* in_sizes, int n_in,
                              void* d_out, int out_size) {
    (void)in_sizes; (void)n_in; (void)out_size;
    const float* x  = (const float*)d_in[0];
    const float* Wq = (const float*)d_in[1];
    const float* Wk = (const float*)d_in[2];
    const float* Wv = (const float*)d_in[3];
    const float* Wo = (const float*)d_in[4];
    float* out = (float*)d_out;

    cudaFuncSetAttribute(flash_attn, cudaFuncAttributeMaxDynamicSharedMemorySize,
                         ATT_SMEM_BYTES);

    dim3 gqkv(E_ / 128, M_ / 128, 3);
    gemm_qkv_mma<<<gqkv, 256, GEMM_SMEM>>>(x, Wq, Wk, Wv);

    dim3 gatt(S_ / AQ, B_ * H_);
    flash_attn<<<gatt, 256, ATT_SMEM_BYTES>>>();

    dim3 gout(E_ / 128, M_ / 128);
    gemm_out_mma<<<gout, 256, GEMM_SMEM>>>(Wo, out);
}

// round 6
// speedup vs baseline: 2.0923x; 1.3166x over previous
#include <cuda_runtime.h>
#include <math.h>
#include <stdint.h>

// Problem constants
#define B_ 2
#define S_ 2048
#define E_ 2048
#define H_ 16
#define D_ 128
#define M_ (B_*S_)   // 4096 rows

// ---------------------------------------------------------------------------
// Scratch (no allocations allowed -> __device__ globals)
// ---------------------------------------------------------------------------
__device__ float g_Q[(size_t)M_ * E_];
__device__ float g_K[(size_t)M_ * E_];
__device__ float g_V[(size_t)M_ * E_];
__device__ float g_O[(size_t)M_ * E_];

// ===========================================================================
// Warp-level helpers (base sm_103 ISA: ldmatrix + mma.sync, NO tcgen05)
// ===========================================================================
__device__ __forceinline__ uint32_t smem_u32(const void* p) {
    uint32_t a;
    asm("{ .reg .u64 t; cvta.to.shared.u64 t, %1; cvt.u32.u64 %0, t; }"
        : "=r"(a) : "l"(p));
    return a;
}

__device__ __forceinline__ void ldsm4(uint32_t* r, uint32_t addr) {
    asm volatile("ldmatrix.sync.aligned.m8n8.x4.shared.b16 {%0,%1,%2,%3}, [%4];"
                 : "=r"(r[0]), "=r"(r[1]), "=r"(r[2]), "=r"(r[3]) : "r"(addr));
}

__device__ __forceinline__ void ldsm4t(uint32_t* r, uint32_t addr) {
    asm volatile("ldmatrix.sync.aligned.m8n8.x4.trans.shared.b16 {%0,%1,%2,%3}, [%4];"
                 : "=r"(r[0]), "=r"(r[1]), "=r"(r[2]), "=r"(r[3]) : "r"(addr));
}

__device__ __forceinline__ void mma_bf16(float* c, const uint32_t* a,
                                         const uint32_t* b) {
    asm volatile(
        "mma.sync.aligned.m16n8k16.row.col.f32.bf16.bf16.f32 "
        "{%0,%1,%2,%3}, {%4,%5,%6,%7}, {%8,%9}, {%0,%1,%2,%3};"
        : "+f"(c[0]), "+f"(c[1]), "+f"(c[2]), "+f"(c[3])
        : "r"(a[0]), "r"(a[1]), "r"(a[2]), "r"(a[3]), "r"(b[0]), "r"(b[1]));
}

// fp32 -> bf16(hi) + bf16(lo), round-to-nearest-even, manual (data is finite)
__device__ __forceinline__ void bsplit(float x, uint32_t& h16, uint32_t& l16) {
    uint32_t u = __float_as_uint(x);
    h16 = (u + 0x7fffu + ((u >> 16) & 1u)) >> 16;
    float hf = __uint_as_float(h16 << 16);
    float lf = x - hf;
    uint32_t v = __float_as_uint(lf);
    l16 = (v + 0x7fffu + ((v >> 16) & 1u)) >> 16;
}

// pack two (hi,lo) splits of consecutive elements into hi-word / lo-word
__device__ __forceinline__ void bpack2(float e, float o, uint32_t& hw, uint32_t& lw) {
    uint32_t he, le, ho, lo;
    bsplit(e, he, le);
    bsplit(o, ho, lo);
    hw = he | (ho << 16);
    lw = le | (lo << 16);
}

// ===========================================================================
// bf16 mma.sync GEMM with 3-pass error compensation (unchanged from R5):
//   C[M,N] = A[M,K] @ W[N,K]^T
// ===========================================================================
#define GK 32
#define NCHUNK (E_ / GK)        // 64
#define TROW 80                 // bytes per smem tile row
#define TILEB (128 * TROW)      // 10240
#define GEMM_SMEM (4 * TILEB)   // 40960

__device__ __forceinline__ void gemm_mma_body(const float* __restrict__ A,
                                              const float* __restrict__ W,
                                              float* __restrict__ C) {
    extern __shared__ char dsm[];
    const uint32_t sAh = smem_u32(dsm);
    const uint32_t sAl = sAh + TILEB;
    const uint32_t sWh = sAh + 2 * TILEB;
    const uint32_t sWl = sAh + 3 * TILEB;

    const int tid  = threadIdx.x;
    const int lane = tid & 31;
    const int wid  = tid >> 5;
    const int wm   = (wid & 1) * 64;
    const int wn   = (wid >> 1) * 32;
    const int row0 = blockIdx.y * 128;
    const int col0 = blockIdx.x * 128;

    const int lr8 = lane & 7;
    const uint32_t aBase = (uint32_t)((wm + lr8 + 8 * ((lane >> 3) & 1)) * TROW
                                      + (lane >> 4) * 16);
    const uint32_t bBase = (uint32_t)((wn + lr8 + 8 * (lane >> 4)) * TROW
                                      + ((lane >> 3) & 1) * 16);

    const int glr = tid >> 1;
    const int gkq = (tid & 1) * 16;
    const float* Ag = A + (size_t)(row0 + glr) * E_ + gkq;
    const float* Wg = W + (size_t)(col0 + glr) * E_ + gkq;
    const uint32_t stOff = (uint32_t)(glr * TROW + (gkq >> 3) * 16);

    float acc[4][4][4];
#pragma unroll
    for (int i = 0; i < 4; i++)
#pragma unroll
        for (int j = 0; j < 4; j++)
#pragma unroll
            for (int q = 0; q < 4; q++) acc[i][j][q] = 0.0f;

    float4 rA[4], rW[4];
#pragma unroll
    for (int j = 0; j < 4; j++) {
        rA[j] = *(const float4*)(Ag + j * 4);
        rW[j] = *(const float4*)(Wg + j * 4);
    }

    for (int c = 0; c < NCHUNK; ++c) {
        __syncthreads();
        {
            uint4 h0, l0, h1, l1;
            bpack2(rA[0].x, rA[0].y, h0.x, l0.x);
            bpack2(rA[0].z, rA[0].w, h0.y, l0.y);
            bpack2(rA[1].x, rA[1].y, h0.z, l0.z);
            bpack2(rA[1].z, rA[1].w, h0.w, l0.w);
            bpack2(rA[2].x, rA[2].y, h1.x, l1.x);
            bpack2(rA[2].z, rA[2].w, h1.y, l1.y);
            bpack2(rA[3].x, rA[3].y, h1.z, l1.z);
            bpack2(rA[3].z, rA[3].w, h1.w, l1.w);
            *(uint4*)(dsm + stOff)                  = h0;
            *(uint4*)(dsm + stOff + 16)             = h1;
            *(uint4*)(dsm + TILEB + stOff)          = l0;
            *(uint4*)(dsm + TILEB + stOff + 16)     = l1;
            bpack2(rW[0].x, rW[0].y, h0.x, l0.x);
            bpack2(rW[0].z, rW[0].w, h0.y, l0.y);
            bpack2(rW[1].x, rW[1].y, h0.z, l0.z);
            bpack2(rW[1].z, rW[1].w, h0.w, l0.w);
            bpack2(rW[2].x, rW[2].y, h1.x, l1.x);
            bpack2(rW[2].z, rW[2].w, h1.y, l1.y);
            bpack2(rW[3].x, rW[3].y, h1.z, l1.z);
            bpack2(rW[3].z, rW[3].w, h1.w, l1.w);
            *(uint4*)(dsm + 2 * TILEB + stOff)      = h0;
            *(uint4*)(dsm + 2 * TILEB + stOff + 16) = h1;
            *(uint4*)(dsm + 3 * TILEB + stOff)      = l0;
            *(uint4*)(dsm + 3 * TILEB + stOff + 16) = l1;
        }
        __syncthreads();

        if (c + 1 < NCHUNK) {
            const float* An = Ag + (c + 1) * GK;
            const float* Wn = Wg + (c + 1) * GK;
#pragma unroll
            for (int j = 0; j < 4; j++) {
                rA[j] = *(const float4*)(An + j * 4);
                rW[j] = *(const float4*)(Wn + j * 4);
            }
        }

#pragma unroll
        for (int kk = 0; kk < 2; ++kk) {
            uint32_t ah[4][4], al[4][4];
#pragma unroll
            for (int mf = 0; mf < 4; mf++) {
                ldsm4(ah[mf], sAh + aBase + (uint32_t)(mf * 16 * TROW + kk * 32));
                ldsm4(al[mf], sAl + aBase + (uint32_t)(mf * 16 * TROW + kk * 32));
            }
            uint32_t bh[2][4], bl[2][4];
#pragma unroll
            for (int p = 0; p < 2; p++) {
                ldsm4(bh[p], sWh + bBase + (uint32_t)(p * 16 * TROW + kk * 32));
                ldsm4(bl[p], sWl + bBase + (uint32_t)(p * 16 * TROW + kk * 32));
            }
#pragma unroll
            for (int p = 0; p < 2; p++)
#pragma unroll
                for (int q = 0; q < 2; q++) {
                    const int nf = p * 2 + q;
#pragma unroll
                    for (int mf = 0; mf < 4; mf++) {
                        mma_bf16(acc[mf][nf], ah[mf], &bh[p][q * 2]);
                        mma_bf16(acc[mf][nf], ah[mf], &bl[p][q * 2]);
                        mma_bf16(acc[mf][nf], al[mf], &bh[p][q * 2]);
                    }
                }
        }
    }

    const int cr = lane >> 2;
    const int cc = (lane & 3) * 2;
#pragma unroll
    for (int mf = 0; mf < 4; mf++) {
#pragma unroll
        for (int nf = 0; nf < 4; nf++) {
            float* p0 = C + (size_t)(row0 + wm + mf * 16 + cr) * E_
                          + col0 + wn + nf * 8 + cc;
            float* p1 = p0 + 8 * E_;
            *(float2*)p0 = make_float2(acc[mf][nf][0], acc[mf][nf][1]);
            *(float2*)p1 = make_float2(acc[mf][nf][2], acc[mf][nf][3]);
        }
    }
}

__global__ __launch_bounds__(256, 1)
void gemm_qkv_mma(const float* __restrict__ x,
                  const float* __restrict__ Wq,
                  const float* __restrict__ Wk,
                  const float* __restrict__ Wv) {
    const float* W = (blockIdx.z == 0) ? Wq : ((blockIdx.z == 1) ? Wk : Wv);
    float* C       = (blockIdx.z == 0) ? g_Q : ((blockIdx.z == 1) ? g_K : g_V);
    gemm_mma_body(x, W, C);
}

__global__ __launch_bounds__(256, 1)
void gemm_out_mma(const float* __restrict__ Wo, float* __restrict__ out) {
    gemm_mma_body(g_O, Wo, out);
}

// ===========================================================================
// Flash attention (causal) on bf16 mma.sync with 3-pass compensation.
// Block: 256 threads (8 warps), Q-tile 128 rows (16/warp), KV-tile 64 keys.
// QK^T: A=Q (hi/lo ldmatrix), B=K (hi/lo ldmatrix non-trans).
// P stays in registers (S C-frag == PV A-frag after bf16 repack).
// PV:   B=V via ldmatrix.trans on row-major [key][d] tiles (hi/lo).
// ===========================================================================
#define FST 272                 // smem row stride bytes (256 data + 16 pad)
#define SQH 0
#define SQL (128 * FST)         // 34816
#define SKH (2 * 128 * FST)     // 69632
#define SKL (SKH + 64 * FST)    // 87040
#define SVH (SKL + 64 * FST)    // 104448
#define SVL (SVH + 64 * FST)    // 121856
#define FA_SMEM (SVL + 64 * FST)// 139264

__global__ __launch_bounds__(256, 1)
void flash_attn_mma() {
    extern __shared__ char fsm[];
    const uint32_t smu = smem_u32(fsm);

    const int tid  = threadIdx.x;
    const int lane = tid & 31;
    const int w    = tid >> 5;
    const int wq   = w * 16;                // warp's q-row offset in tile
    const int bh   = blockIdx.y;
    const int b    = bh >> 4;
    const int h    = bh & 15;
    const int q0   = blockIdx.x * 128;
    const float scale = 0.08838834764831845f;   // 1/sqrt(128)
    const size_t base = (size_t)b * S_ * E_ + (size_t)h * D_;

    // ---- load + scale + split Q tile (128 x 128) ----
    {
        const int row = tid >> 1;
        const int half = tid & 1;
        const float* Qg = g_Q + base + (size_t)(q0 + row) * E_ + half * 64;
        char* qh = fsm + SQH + row * FST + half * 128;
        char* ql = fsm + SQL + row * FST + half * 128;
#pragma unroll
        for (int j = 0; j < 16; j++) {
            float4 v = ((const float4*)Qg)[j];
            uint32_t h0, l0, h1, l1;
            bpack2(v.x * scale, v.y * scale, h0, l0);
            bpack2(v.z * scale, v.w * scale, h1, l1);
            *(uint2*)(qh + j * 8) = make_uint2(h0, h1);
            *(uint2*)(ql + j * 8) = make_uint2(l0, l1);
        }
    }

    float m0 = -1e30f, m1 = -1e30f, l0s = 0.0f, l1s = 0.0f;
    float oacc[16][4];
#pragma unroll
    for (int jn = 0; jn < 16; jn++)
#pragma unroll
        for (int q = 0; q < 4; q++) oacc[jn][q] = 0.0f;

    const int r0loc = q0 + wq + (lane >> 2);    // this thread's global q rows
    const int r1loc = r0loc + 8;
    const int nkt = q0 / 64 + 2;

    for (int kt = 0; kt < nkt; kt++) {
        const int k0 = kt * 64;
        __syncthreads();
        // ---- load + split K and V tiles (64 x 128 each) ----
        {
            const int row = tid >> 2;
            const int qd  = tid & 3;
            const float* Kg = g_K + base + (size_t)(k0 + row) * E_ + qd * 32;
            const float* Vg = g_V + base + (size_t)(k0 + row) * E_ + qd * 32;
            char* kh = fsm + SKH + row * FST + qd * 64;
            char* kl = fsm + SKL + row * FST + qd * 64;
            char* vh = fsm + SVH + row * FST + qd * 64;
            char* vl = fsm + SVL + row * FST + qd * 64;
#pragma unroll
            for (int j = 0; j < 8; j++) {
                float4 kv = ((const float4*)Kg)[j];
                uint32_t h0, l0, h1, l1;
                bpack2(kv.x, kv.y, h0, l0);
                bpack2(kv.z, kv.w, h1, l1);
                *(uint2*)(kh + j * 8) = make_uint2(h0, h1);
                *(uint2*)(kl + j * 8) = make_uint2(l0, l1);
                float4 vv = ((const float4*)Vg)[j];
                bpack2(vv.x, vv.y, h0, l0);
                bpack2(vv.z, vv.w, h1, l1);
                *(uint2*)(vh + j * 8) = make_uint2(h0, h1);
                *(uint2*)(vl + j * 8) = make_uint2(l0, l1);
            }
        }
        __syncthreads();

        if (k0 <= q0 + wq + 15) {     // warp has at least one unmasked element
            // ---- S = Q K^T (3-pass bf16) ----
            float sacc[8][4];
#pragma unroll
            for (int j = 0; j < 8; j++)
#pragma unroll
                for (int q = 0; q < 4; q++) sacc[j][q] = 0.0f;

            const uint32_t qOff = smu + (uint32_t)((wq + (lane & 15)) * FST
                                                   + (lane >> 4) * 16);
            const uint32_t kRow = (uint32_t)((lane & 7) + 8 * (lane >> 4));
            const uint32_t kCol = (uint32_t)(((lane >> 3) & 1) * 16);
#pragma unroll
            for (int kk = 0; kk < 8; kk++) {
                uint32_t qh[4], ql[4];
                ldsm4(qh, qOff + SQH + kk * 32);
                ldsm4(ql, qOff + SQL + kk * 32);
#pragma unroll
                for (int kb = 0; kb < 4; kb++) {
                    const uint32_t ka = smu + (uint32_t)((kb * 16 + kRow) * FST)
                                        + kCol + (uint32_t)(kk * 32);
                    uint32_t khf[4], klf[4];
                    ldsm4(khf, ka + SKH);
                    ldsm4(klf, ka + SKL);
                    mma_bf16(sacc[2 * kb],     qh, &khf[0]);
                    mma_bf16(sacc[2 * kb],     qh, &klf[0]);
                    mma_bf16(sacc[2 * kb],     ql, &khf[0]);
                    mma_bf16(sacc[2 * kb + 1], qh, &khf[2]);
                    mma_bf16(sacc[2 * kb + 1], qh, &klf[2]);
                    mma_bf16(sacc[2 * kb + 1], ql, &khf[2]);
                }
            }

            // ---- causal mask (only near-diagonal tiles) ----
            if (k0 + 63 > q0 + wq) {
#pragma unroll
                for (int j = 0; j < 8; j++) {
                    const int cb = k0 + 8 * j + (lane & 3) * 2;
                    if (cb     > r0loc) sacc[j][0] = -1e9f;
                    if (cb + 1 > r0loc) sacc[j][1] = -1e9f;
                    if (cb     > r1loc) sacc[j][2] = -1e9f;
                    if (cb + 1 > r1loc) sacc[j][3] = -1e9f;
                }
            }

            // ---- online softmax (2 rows per thread) ----
            float rm0 = -1e30f, rm1 = -1e30f;
#pragma unroll
            for (int j = 0; j < 8; j++) {
                rm0 = fmaxf(rm0, fmaxf(sacc[j][0], sacc[j][1]));
                rm1 = fmaxf(rm1, fmaxf(sacc[j][2], sacc[j][3]));
            }
            rm0 = fmaxf(rm0, __shfl_xor_sync(0xffffffffu, rm0, 1));
            rm0 = fmaxf(rm0, __shfl_xor_sync(0xffffffffu, rm0, 2));
            rm1 = fmaxf(rm1, __shfl_xor_sync(0xffffffffu, rm1, 1));
            rm1 = fmaxf(rm1, __shfl_xor_sync(0xffffffffu, rm1, 2));
            const float mn0 = fmaxf(m0, rm0);
            const float mn1 = fmaxf(m1, rm1);
            const float c0 = __expf(m0 - mn0);
            const float c1 = __expf(m1 - mn1);
            m0 = mn0; m1 = mn1;
            float rs0 = 0.0f, rs1 = 0.0f;
#pragma unroll
            for (int j = 0; j < 8; j++) {
                sacc[j][0] = __expf(sacc[j][0] - mn0); rs0 += sacc[j][0];
                sacc[j][1] = __expf(sacc[j][1] - mn0); rs0 += sacc[j][1];
                sacc[j][2] = __expf(sacc[j][2] - mn1); rs1 += sacc[j][2];
                sacc[j][3] = __expf(sacc[j][3] - mn1); rs1 += sacc[j][3];
            }
            rs0 += __shfl_xor_sync(0xffffffffu, rs0, 1);
            rs0 += __shfl_xor_sync(0xffffffffu, rs0, 2);
            rs1 += __shfl_xor_sync(0xffffffffu, rs1, 1);
            rs1 += __shfl_xor_sync(0xffffffffu, rs1, 2);
            l0s = l0s * c0 + rs0;
            l1s = l1s * c1 + rs1;
#pragma unroll
            for (int jn = 0; jn < 16; jn++) {
                oacc[jn][0] *= c0; oacc[jn][1] *= c0;
                oacc[jn][2] *= c1; oacc[jn][3] *= c1;
            }

            // ---- O += P V (3-pass bf16; P repacked from S regs) ----
            const uint32_t vRowCol = smu + (uint32_t)((lane & 15) * FST
                                                      + (lane >> 4) * 16);
#pragma unroll
            for (int kk = 0; kk < 4; kk++) {
                uint32_t ph[4], pl[4];
                bpack2(sacc[2 * kk][0],     sacc[2 * kk][1],     ph[0], pl[0]);
                bpack2(sacc[2 * kk][2],     sacc[2 * kk][3],     ph[1], pl[1]);
                bpack2(sacc[2 * kk + 1][0], sacc[2 * kk + 1][1], ph[2], pl[2]);
                bpack2(sacc[2 * kk + 1][2], sacc[2 * kk + 1][3], ph[3], pl[3]);
#pragma unroll
                for (int jp = 0; jp < 8; jp++) {
                    const uint32_t va = vRowCol + (uint32_t)(kk * 16 * FST)
                                        + (uint32_t)(jp * 32);
                    uint32_t vhf[4], vlf[4];
                    ldsm4t(vhf, va + SVH);
                    ldsm4t(vlf, va + SVL);
                    mma_bf16(oacc[2 * jp],     ph, &vhf[0]);
                    mma_bf16(oacc[2 * jp],     ph, &vlf[0]);
                    mma_bf16(oacc[2 * jp],     pl, &vhf[0]);
                    mma_bf16(oacc[2 * jp + 1], ph, &vhf[2]);
                    mma_bf16(oacc[2 * jp + 1], ph, &vlf[2]);
                    mma_bf16(oacc[2 * jp + 1], pl, &vhf[2]);
                }
            }
        }
    }

    // ---- epilogue: normalize + write head slice into g_O ----
    const float inv0 = 1.0f / l0s;
    const float inv1 = 1.0f / l1s;
    float* o0 = g_O + base + (size_t)r0loc * E_;
    float* o1 = g_O + base + (size_t)r1loc * E_;
#pragma unroll
    for (int jn = 0; jn < 16; jn++) {
        const int col = 8 * jn + (lane & 3) * 2;
        *(float2*)(o0 + col) = make_float2(oacc[jn][0] * inv0, oacc[jn][1] * inv0);
        *(float2*)(o1 + col) = make_float2(oacc[jn][2] * inv1, oacc[jn][3] * inv1);
    }
}

// ---------------------------------------------------------------------------
// Launch
// ---------------------------------------------------------------------------
extern "C" void kernel_launch(void* const* d_in, const int* in_sizes, int n_in,
                              void* d_out, int out_size) {
    (void)in_sizes; (void)n_in; (void)out_size;
    const float* x  = (const float*)d_in[0];
    const float* Wq = (const float*)d_in[1];
    const float* Wk = (const float*)d_in[2];
    const float* Wv = (const float*)d_in[3];
    const float* Wo = (const float*)d_in[4];
    float* out = (float*)d_out;

    cudaFuncSetAttribute(flash_attn_mma,
                         cudaFuncAttributeMaxDynamicSharedMemorySize, FA_SMEM);

    dim3 gqkv(E_ / 128, M_ / 128, 3);
    gemm_qkv_mma<<<gqkv, 256, GEMM_SMEM>>>(x, Wq, Wk, Wv);

    dim3 gatt(S_ / 128, B_ * H_);
    flash_attn_mma<<<gatt, 256, FA_SMEM>>>();

    dim3 gout(E_ / 128, M_ / 128);
    gemm_out_mma<<<gout, 256, GEMM_SMEM>>>(Wo, out);
}

// round 7
// speedup vs baseline: 2.5790x; 1.2326x over previous
#include <cuda_runtime.h>
#include <math.h>
#include <stdint.h>

// Problem constants
#define B_ 2
#define S_ 2048
#define E_ 2048
#define H_ 16
#define D_ 128
#define M_ (B_*S_)   // 4096 rows

typedef unsigned short u16;
typedef unsigned int   u32;

// ---------------------------------------------------------------------------
// Scratch (no allocations allowed -> __device__ globals), all bf16 hi/lo pairs
// ---------------------------------------------------------------------------
__device__ u16 g_xh[(size_t)M_ * E_],  g_xl[(size_t)M_ * E_];
__device__ u16 g_Wqh[(size_t)E_ * E_], g_Wql[(size_t)E_ * E_];
__device__ u16 g_Wkh[(size_t)E_ * E_], g_Wkl[(size_t)E_ * E_];
__device__ u16 g_Wvh[(size_t)E_ * E_], g_Wvl[(size_t)E_ * E_];
__device__ u16 g_Woh[(size_t)E_ * E_], g_Wol[(size_t)E_ * E_];
__device__ u16 g_Qh[(size_t)M_ * E_],  g_Ql[(size_t)M_ * E_];
__device__ u16 g_Kh[(size_t)M_ * E_],  g_Kl[(size_t)M_ * E_];
__device__ u16 g_Vh[(size_t)M_ * E_],  g_Vl[(size_t)M_ * E_];
__device__ u16 g_Oh[(size_t)M_ * E_],  g_Ol[(size_t)M_ * E_];

// ===========================================================================
// Helpers (base sm_103 ISA: ldmatrix + mma.sync + cp.async; NO tcgen05)
// ===========================================================================
__device__ __forceinline__ u32 smem_u32(const void* p) {
    u32 a;
    asm("{ .reg .u64 t; cvta.to.shared.u64 t, %1; cvt.u32.u64 %0, t; }"
        : "=r"(a) : "l"(p));
    return a;
}

__device__ __forceinline__ void ldsm4(u32* r, u32 addr) {
    asm volatile("ldmatrix.sync.aligned.m8n8.x4.shared.b16 {%0,%1,%2,%3}, [%4];"
                 : "=r"(r[0]), "=r"(r[1]), "=r"(r[2]), "=r"(r[3]) : "r"(addr));
}

__device__ __forceinline__ void ldsm4t(u32* r, u32 addr) {
    asm volatile("ldmatrix.sync.aligned.m8n8.x4.trans.shared.b16 {%0,%1,%2,%3}, [%4];"
                 : "=r"(r[0]), "=r"(r[1]), "=r"(r[2]), "=r"(r[3]) : "r"(addr));
}

__device__ __forceinline__ void mma_bf16(float* c, const u32* a, const u32* b) {
    asm volatile(
        "mma.sync.aligned.m16n8k16.row.col.f32.bf16.bf16.f32 "
        "{%0,%1,%2,%3}, {%4,%5,%6,%7}, {%8,%9}, {%0,%1,%2,%3};"
        : "+f"(c[0]), "+f"(c[1]), "+f"(c[2]), "+f"(c[3])
        : "r"(a[0]), "r"(a[1]), "r"(a[2]), "r"(a[3]), "r"(b[0]), "r"(b[1]));
}

__device__ __forceinline__ void cp16(u32 smem, const void* gptr) {
    asm volatile("cp.async.cg.shared.global [%0], [%1], 16;"
                 :: "r"(smem), "l"(__cvta_generic_to_global(gptr)));
}
#define CP_COMMIT() asm volatile("cp.async.commit_group;" ::: "memory")
#define CP_WAIT(n)  asm volatile("cp.async.wait_group %0;" :: "n"(n) : "memory")

// fp32 -> bf16(hi) + bf16(lo), round-to-nearest-even
__device__ __forceinline__ void bsplit(float x, u32& h16, u32& l16) {
    u32 u = __float_as_uint(x);
    h16 = (u + 0x7fffu + ((u >> 16) & 1u)) >> 16;
    float hf = __uint_as_float(h16 << 16);
    float lf = x - hf;
    u32 v = __float_as_uint(lf);
    l16 = (v + 0x7fffu + ((v >> 16) & 1u)) >> 16;
}

__device__ __forceinline__ void bpack2(float e, float o, u32& hw, u32& lw) {
    u32 he, le, ho, lo;
    bsplit(e, he, le);
    bsplit(o, ho, lo);
    hw = he | (ho << 16);
    lw = le | (lo << 16);
}

// ===========================================================================
// Pre-split: fp32 tensor -> bf16 hi/lo arrays (run once per tensor)
// ===========================================================================
__global__ void bf16_split_kernel(const float* __restrict__ s,
                                  u16* __restrict__ h, u16* __restrict__ l,
                                  int n4) {
    int i = blockIdx.x * blockDim.x + threadIdx.x;
    if (i < n4) {
        float4 v = ((const float4*)s)[i];
        u32 h0, l0, h1, l1;
        bpack2(v.x, v.y, h0, l0);
        bpack2(v.z, v.w, h1, l1);
        *(uint2*)(h + (size_t)i * 4) = make_uint2(h0, h1);
        *(uint2*)(l + (size_t)i * 4) = make_uint2(l0, l1);
    }
}

// ===========================================================================
// bf16 mma.sync GEMM, 3-pass compensation, inputs pre-split:
//   C[M,N] = A[M,K] @ W[N,K]^T
// 128x128 tile, k-chunk 32, 256 threads (8 warps of 64x32).
// BF16OUT=1: write Ch/Cl (hi/lo split of osc*acc). BF16OUT=0: write fp32 Cf.
// ===========================================================================
#define GK 32
#define NCHUNK (E_ / GK)        // 64
#define TROW 80                 // bytes per smem tile row (64 data + 16 pad)
#define TILEB (128 * TROW)      // 10240
#define GEMM_SMEM (4 * TILEB)   // 40960

template<int BF16OUT>
__device__ __forceinline__ void gemm_body_b(const u16* __restrict__ Ah,
                                            const u16* __restrict__ Al,
                                            const u16* __restrict__ Wh,
                                            const u16* __restrict__ Wl,
                                            float* __restrict__ Cf,
                                            u16* __restrict__ Ch,
                                            u16* __restrict__ Cl,
                                            float osc) {
    extern __shared__ char dsm[];
    const u32 sAh = smem_u32(dsm);
    const u32 sAl = sAh + TILEB;
    const u32 sWh = sAh + 2 * TILEB;
    const u32 sWl = sAh + 3 * TILEB;

    const int tid  = threadIdx.x;
    const int lane = tid & 31;
    const int wid  = tid >> 5;
    const int wm   = (wid & 1) * 64;
    const int wn   = (wid >> 1) * 32;
    const int row0 = blockIdx.y * 128;
    const int col0 = blockIdx.x * 128;

    const int lr8 = lane & 7;
    const u32 aBase = (u32)((wm + lr8 + 8 * ((lane >> 3) & 1)) * TROW
                            + (lane >> 4) * 16);
    const u32 bBase = (u32)((wn + lr8 + 8 * (lane >> 4)) * TROW
                            + ((lane >> 3) & 1) * 16);

    const int glr = tid >> 1;          // smem row 0..127
    const int gh  = tid & 1;           // 16-elem half of the 32-elem row
    const u16* Ap  = Ah + (size_t)(row0 + glr) * E_;
    const u16* Alp = Al + (size_t)(row0 + glr) * E_;
    const u16* Wp  = Wh + (size_t)(col0 + glr) * E_;
    const u16* Wlp = Wl + (size_t)(col0 + glr) * E_;
    const u32 stOff = (u32)(glr * TROW + gh * 32);

    float acc[4][4][4];
#pragma unroll
    for (int i = 0; i < 4; i++)
#pragma unroll
        for (int j = 0; j < 4; j++)
#pragma unroll
            for (int q = 0; q < 4; q++) acc[i][j][q] = 0.0f;

    uint4 rAh[2], rAl[2], rWh[2], rWl[2];
    {
        const int gk = gh * 16;
        rAh[0] = *(const uint4*)(Ap + gk);  rAh[1] = *(const uint4*)(Ap + gk + 8);
        rAl[0] = *(const uint4*)(Alp + gk); rAl[1] = *(const uint4*)(Alp + gk + 8);
        rWh[0] = *(const uint4*)(Wp + gk);  rWh[1] = *(const uint4*)(Wp + gk + 8);
        rWl[0] = *(const uint4*)(Wlp + gk); rWl[1] = *(const uint4*)(Wlp + gk + 8);
    }

    for (int c = 0; c < NCHUNK; ++c) {
        __syncthreads();
        *(uint4*)(dsm + stOff)                  = rAh[0];
        *(uint4*)(dsm + stOff + 16)             = rAh[1];
        *(uint4*)(dsm + TILEB + stOff)          = rAl[0];
        *(uint4*)(dsm + TILEB + stOff + 16)     = rAl[1];
        *(uint4*)(dsm + 2 * TILEB + stOff)      = rWh[0];
        *(uint4*)(dsm + 2 * TILEB + stOff + 16) = rWh[1];
        *(uint4*)(dsm + 3 * TILEB + stOff)      = rWl[0];
        *(uint4*)(dsm + 3 * TILEB + stOff + 16) = rWl[1];
        __syncthreads();

        if (c + 1 < NCHUNK) {
            const int gk = (c + 1) * GK + gh * 16;
            rAh[0] = *(const uint4*)(Ap + gk);  rAh[1] = *(const uint4*)(Ap + gk + 8);
            rAl[0] = *(const uint4*)(Alp + gk); rAl[1] = *(const uint4*)(Alp + gk + 8);
            rWh[0] = *(const uint4*)(Wp + gk);  rWh[1] = *(const uint4*)(Wp + gk + 8);
            rWl[0] = *(const uint4*)(Wlp + gk); rWl[1] = *(const uint4*)(Wlp + gk + 8);
        }

#pragma unroll
        for (int kk = 0; kk < 2; ++kk) {
            u32 ah[4][4], al[4][4];
#pragma unroll
            for (int mf = 0; mf < 4; mf++) {
                ldsm4(ah[mf], sAh + aBase + (u32)(mf * 16 * TROW + kk * 32));
                ldsm4(al[mf], sAl + aBase + (u32)(mf * 16 * TROW + kk * 32));
            }
            u32 bh[2][4], bl[2][4];
#pragma unroll
            for (int p = 0; p < 2; p++) {
                ldsm4(bh[p], sWh + bBase + (u32)(p * 16 * TROW + kk * 32));
                ldsm4(bl[p], sWl + bBase + (u32)(p * 16 * TROW + kk * 32));
            }
#pragma unroll
            for (int p = 0; p < 2; p++)
#pragma unroll
                for (int q = 0; q < 2; q++) {
                    const int nf = p * 2 + q;
#pragma unroll
                    for (int mf = 0; mf < 4; mf++) {
                        mma_bf16(acc[mf][nf], ah[mf], &bh[p][q * 2]);
                        mma_bf16(acc[mf][nf], ah[mf], &bl[p][q * 2]);
                        mma_bf16(acc[mf][nf], al[mf], &bh[p][q * 2]);
                    }
                }
        }
    }

    const int cr = lane >> 2;
    const int cc = (lane & 3) * 2;
#pragma unroll
    for (int mf = 0; mf < 4; mf++) {
#pragma unroll
        for (int nf = 0; nf < 4; nf++) {
            const size_t o0 = (size_t)(row0 + wm + mf * 16 + cr) * E_
                              + col0 + wn + nf * 8 + cc;
            const size_t o1 = o0 + (size_t)8 * E_;
            if (BF16OUT) {
                u32 hw, lw;
                bpack2(acc[mf][nf][0] * osc, acc[mf][nf][1] * osc, hw, lw);
                *(u32*)(Ch + o0) = hw;
                *(u32*)(Cl + o0) = lw;
                bpack2(acc[mf][nf][2] * osc, acc[mf][nf][3] * osc, hw, lw);
                *(u32*)(Ch + o1) = hw;
                *(u32*)(Cl + o1) = lw;
            } else {
                *(float2*)(Cf + o0) = make_float2(acc[mf][nf][0], acc[mf][nf][1]);
                *(float2*)(Cf + o1) = make_float2(acc[mf][nf][2], acc[mf][nf][3]);
            }
        }
    }
}

__global__ __launch_bounds__(256, 1)
void gemm_qkv_mma() {
    const u16 *Wh, *Wl;
    u16 *Ch, *Cl;
    float sc = 1.0f;
    if (blockIdx.z == 0) {
        Wh = g_Wqh; Wl = g_Wql; Ch = g_Qh; Cl = g_Ql;
        sc = 0.08838834764831845f;   // 1/sqrt(128) folded into Q
    } else if (blockIdx.z == 1) {
        Wh = g_Wkh; Wl = g_Wkl; Ch = g_Kh; Cl = g_Kl;
    } else {
        Wh = g_Wvh; Wl = g_Wvl; Ch = g_Vh; Cl = g_Vl;
    }
    gemm_body_b<1>(g_xh, g_xl, Wh, Wl, nullptr, Ch, Cl, sc);
}

__global__ __launch_bounds__(256, 1)
void gemm_out_mma(float* __restrict__ out) {
    gemm_body_b<0>(g_Oh, g_Ol, g_Woh, g_Wol, out, nullptr, nullptr, 1.0f);
}

// ===========================================================================
// Flash attention (causal), bf16 mma 3-pass, inputs pre-split, cp.async
// 2-stage K/V pipeline. Block: 256 threads (8 warps), Q-tile 128, KV-tile 64.
// ===========================================================================
#define FST 272                     // smem row stride bytes (256 data + 16 pad)
#define SQH_OFF 0
#define SQL_OFF (128 * FST)         // 34816
#define STG_OFF (2 * 128 * FST)     // 69632
#define STG_SZ  (4 * 64 * FST)      // 69632 per stage (Kh,Kl,Vh,Vl)
#define KH_OFF 0
#define KL_OFF (64 * FST)           // 17408
#define VH_OFF (2 * 64 * FST)
#define VL_OFF (3 * 64 * FST)
#define FA_SMEM (STG_OFF + 2 * STG_SZ)   // 208896

__global__ __launch_bounds__(256, 1)
void flash_attn_mma() {
    extern __shared__ char fsm[];
    const u32 smu = smem_u32(fsm);

    const int tid  = threadIdx.x;
    const int lane = tid & 31;
    const int w    = tid >> 5;
    const int wq   = w * 16;
    const int bh   = blockIdx.y;
    const int b    = bh >> 4;
    const int h    = bh & 15;
    const int q0   = blockIdx.x * 128;
    const size_t base = (size_t)b * S_ * E_ + (size_t)h * D_;

    // ---- Q tile loads (cp.async, bf16 hi/lo, already scaled) ----
    {
        const int r = tid >> 1, half = tid & 1;
        const u16* qh = g_Qh + base + (size_t)(q0 + r) * E_ + half * 64;
        const u16* ql = g_Ql + base + (size_t)(q0 + r) * E_ + half * 64;
        const u32 sh = smu + SQH_OFF + (u32)(r * FST + half * 128);
        const u32 sl = smu + SQL_OFF + (u32)(r * FST + half * 128);
#pragma unroll
        for (int j = 0; j < 8; j++) {
            cp16(sh + j * 16, qh + j * 8);
            cp16(sl + j * 16, ql + j * 8);
        }
    }

    const int kvr = tid >> 2;       // 0..63
    const int kvq = tid & 3;        // 64B quarter
    const int nkt = q0 / 64 + 2;

    // issue K/V stage for tile kt
    auto issue_kv = [&](int kt) {
        const size_t g = base + (size_t)(kt * 64 + kvr) * E_ + kvq * 32;
        const u32 sb = smu + STG_OFF + (u32)((kt & 1) * STG_SZ)
                       + (u32)(kvr * FST + kvq * 64);
#pragma unroll
        for (int j = 0; j < 4; j++) {
            cp16(sb + KH_OFF + j * 16, g_Kh + g + j * 8);
            cp16(sb + KL_OFF + j * 16, g_Kl + g + j * 8);
            cp16(sb + VH_OFF + j * 16, g_Vh + g + j * 8);
            cp16(sb + VL_OFF + j * 16, g_Vl + g + j * 8);
        }
    };

    issue_kv(0);
    CP_COMMIT();    // group: Q + kv0

    float m0 = -1e30f, m1 = -1e30f, l0s = 0.0f, l1s = 0.0f;
    float oacc[16][4];
#pragma unroll
    for (int jn = 0; jn < 16; jn++)
#pragma unroll
        for (int q = 0; q < 4; q++) oacc[jn][q] = 0.0f;

    const int r0loc = q0 + wq + (lane >> 2);
    const int r1loc = r0loc + 8;

    const u32 qBase = smu + (u32)((wq + (lane & 15)) * FST + (lane >> 4) * 16);
    const u32 kRow  = (u32)((lane & 7) + 8 * (lane >> 4));
    const u32 kColB = (u32)(((lane >> 3) & 1) * 16);
    const u32 vLane = (u32)((lane & 15) * FST + (lane >> 4) * 16);

    for (int kt = 0; kt < nkt; kt++) {
        const int k0 = kt * 64;
        if (kt + 1 < nkt) {
            issue_kv(kt + 1);
            CP_COMMIT();
            CP_WAIT(1);
        } else {
            CP_WAIT(0);
        }
        __syncthreads();

        if (k0 <= q0 + wq + 15) {
            const u32 stb = smu + STG_OFF + (u32)((kt & 1) * STG_SZ);

            // ---- S = Q K^T (3-pass) ----
            float sacc[8][4];
#pragma unroll
            for (int j = 0; j < 8; j++)
#pragma unroll
                for (int q = 0; q < 4; q++) sacc[j][q] = 0.0f;

#pragma unroll
            for (int kk = 0; kk < 8; kk++) {
                u32 qh[4], ql[4];
                ldsm4(qh, qBase + SQH_OFF + kk * 32);
                ldsm4(ql, qBase + SQL_OFF + kk * 32);
#pragma unroll
                for (int kb = 0; kb < 4; kb++) {
                    const u32 ka = stb + KH_OFF + (u32)((kb * 16 + kRow) * FST)
                                   + kColB + (u32)(kk * 32);
                    u32 khf[4], klf[4];
                    ldsm4(khf, ka);
                    ldsm4(klf, ka + (KL_OFF - KH_OFF));
                    mma_bf16(sacc[2 * kb],     qh, &khf[0]);
                    mma_bf16(sacc[2 * kb],     qh, &klf[0]);
                    mma_bf16(sacc[2 * kb],     ql, &khf[0]);
                    mma_bf16(sacc[2 * kb + 1], qh, &khf[2]);
                    mma_bf16(sacc[2 * kb + 1], qh, &klf[2]);
                    mma_bf16(sacc[2 * kb + 1], ql, &khf[2]);
                }
            }

            // ---- causal mask (near-diagonal tiles only) ----
            if (k0 + 63 > q0 + wq) {
#pragma unroll
                for (int j = 0; j < 8; j++) {
                    const int cb = k0 + 8 * j + (lane & 3) * 2;
                    if (cb     > r0loc) sacc[j][0] = -1e9f;
                    if (cb + 1 > r0loc) sacc[j][1] = -1e9f;
                    if (cb     > r1loc) sacc[j][2] = -1e9f;
                    if (cb + 1 > r1loc) sacc[j][3] = -1e9f;
                }
            }

            // ---- online softmax (2 rows/thread) ----
            float rm0 = -1e30f, rm1 = -1e30f;
#pragma unroll
            for (int j = 0; j < 8; j++) {
                rm0 = fmaxf(rm0, fmaxf(sacc[j][0], sacc[j][1]));
                rm1 = fmaxf(rm1, fmaxf(sacc[j][2], sacc[j][3]));
            }
            rm0 = fmaxf(rm0, __shfl_xor_sync(0xffffffffu, rm0, 1));
            rm0 = fmaxf(rm0, __shfl_xor_sync(0xffffffffu, rm0, 2));
            rm1 = fmaxf(rm1, __shfl_xor_sync(0xffffffffu, rm1, 1));
            rm1 = fmaxf(rm1, __shfl_xor_sync(0xffffffffu, rm1, 2));
            const float mn0 = fmaxf(m0, rm0);
            const float mn1 = fmaxf(m1, rm1);
            const float c0 = __expf(m0 - mn0);
            const float c1 = __expf(m1 - mn1);
            m0 = mn0; m1 = mn1;
            float rs0 = 0.0f, rs1 = 0.0f;
#pragma unroll
            for (int j = 0; j < 8; j++) {
                sacc[j][0] = __expf(sacc[j][0] - mn0); rs0 += sacc[j][0];
                sacc[j][1] = __expf(sacc[j][1] - mn0); rs0 += sacc[j][1];
                sacc[j][2] = __expf(sacc[j][2] - mn1); rs1 += sacc[j][2];
                sacc[j][3] = __expf(sacc[j][3] - mn1); rs1 += sacc[j][3];
            }
            rs0 += __shfl_xor_sync(0xffffffffu, rs0, 1);
            rs0 += __shfl_xor_sync(0xffffffffu, rs0, 2);
            rs1 += __shfl_xor_sync(0xffffffffu, rs1, 1);
            rs1 += __shfl_xor_sync(0xffffffffu, rs1, 2);
            l0s = l0s * c0 + rs0;
            l1s = l1s * c1 + rs1;
#pragma unroll
            for (int jn = 0; jn < 16; jn++) {
                oacc[jn][0] *= c0; oacc[jn][1] *= c0;
                oacc[jn][2] *= c1; oacc[jn][3] *= c1;
            }

            // ---- O += P V (3-pass; P repacked from S regs) ----
#pragma unroll
            for (int kk = 0; kk < 4; kk++) {
                u32 ph[4], pl[4];
                bpack2(sacc[2 * kk][0],     sacc[2 * kk][1],     ph[0], pl[0]);
                bpack2(sacc[2 * kk][2],     sacc[2 * kk][3],     ph[1], pl[1]);
                bpack2(sacc[2 * kk + 1][0], sacc[2 * kk + 1][1], ph[2], pl[2]);
                bpack2(sacc[2 * kk + 1][2], sacc[2 * kk + 1][3], ph[3], pl[3]);
#pragma unroll
                for (int jp = 0; jp < 8; jp++) {
                    const u32 va = stb + VH_OFF + vLane
                                   + (u32)(kk * 16 * FST + jp * 32);
                    u32 vhf[4], vlf[4];
                    ldsm4t(vhf, va);
                    ldsm4t(vlf, va + (VL_OFF - VH_OFF));
                    mma_bf16(oacc[2 * jp],     ph, &vhf[0]);
                    mma_bf16(oacc[2 * jp],     ph, &vlf[0]);
                    mma_bf16(oacc[2 * jp],     pl, &vhf[0]);
                    mma_bf16(oacc[2 * jp + 1], ph, &vhf[2]);
                    mma_bf16(oacc[2 * jp + 1], ph, &vlf[2]);
                    mma_bf16(oacc[2 * jp + 1], pl, &vhf[2]);
                }
            }
        }
        __syncthreads();
    }

    // ---- epilogue: normalize + split to bf16 hi/lo into g_Oh/g_Ol ----
    const float inv0 = 1.0f / l0s;
    const float inv1 = 1.0f / l1s;
    u16* oh0 = g_Oh + base + (size_t)r0loc * E_;
    u16* ol0 = g_Ol + base + (size_t)r0loc * E_;
    u16* oh1 = g_Oh + base + (size_t)r1loc * E_;
    u16* ol1 = g_Ol + base + (size_t)r1loc * E_;
#pragma unroll
    for (int jn = 0; jn < 16; jn++) {
        const int col = 8 * jn + (lane & 3) * 2;
        u32 hw, lw;
        bpack2(oacc[jn][0] * inv0, oacc[jn][1] * inv0, hw, lw);
        *(u32*)(oh0 + col) = hw;
        *(u32*)(ol0 + col) = lw;
        bpack2(oacc[jn][2] * inv1, oacc[jn][3] * inv1, hw, lw);
        *(u32*)(oh1 + col) = hw;
        *(u32*)(ol1 + col) = lw;
    }
}

// ---------------------------------------------------------------------------
// Launch
// ---------------------------------------------------------------------------
extern "C" void kernel_launch(void* const* d_in, const int* in_sizes, int n_in,
                              void* d_out, int out_size) {
    (void)in_sizes; (void)n_in; (void)out_size;
    const float* x  = (const float*)d_in[0];
    const float* Wq = (const float*)d_in[1];
    const float* Wk = (const float*)d_in[2];
    const float* Wv = (const float*)d_in[3];
    const float* Wo = (const float*)d_in[4];
    float* out = (float*)d_out;

    cudaFuncSetAttribute(flash_attn_mma,
                         cudaFuncAttributeMaxDynamicSharedMemorySize, FA_SMEM);

    // resolve device-global addresses (host-side, not stream ops)
    u16 *xh, *xl, *wqh, *wql, *wkh, *wkl, *wvh, *wvl, *woh, *wol;
    cudaGetSymbolAddress((void**)&xh,  g_xh);
    cudaGetSymbolAddress((void**)&xl,  g_xl);
    cudaGetSymbolAddress((void**)&wqh, g_Wqh);
    cudaGetSymbolAddress((void**)&wql, g_Wql);
    cudaGetSymbolAddress((void**)&wkh, g_Wkh);
    cudaGetSymbolAddress((void**)&wkl, g_Wkl);
    cudaGetSymbolAddress((void**)&wvh, g_Wvh);
    cudaGetSymbolAddress((void**)&wvl, g_Wvl);
    cudaGetSymbolAddress((void**)&woh, g_Woh);
    cudaGetSymbolAddress((void**)&wol, g_Wol);

    const int nx4 = (M_ * E_) / 4;
    const int nw4 = (E_ * E_) / 4;
    bf16_split_kernel<<<(nx4 + 255) / 256, 256>>>(x,  xh,  xl,  nx4);
    bf16_split_kernel<<<(nw4 + 255) / 256, 256>>>(Wq, wqh, wql, nw4);
    bf16_split_kernel<<<(nw4 + 255) / 256, 256>>>(Wk, wkh, wkl, nw4);
    bf16_split_kernel<<<(nw4 + 255) / 256, 256>>>(Wv, wvh, wvl, nw4);
    bf16_split_kernel<<<(nw4 + 255) / 256, 256>>>(Wo, woh, wol, nw4);

    dim3 gqkv(E_ / 128, M_ / 128, 3);
    gemm_qkv_mma<<<gqkv, 256, GEMM_SMEM>>>();

    dim3 gatt(S_ / 128, B_ * H_);
    flash_attn_mma<<<gatt, 256, FA_SMEM>>>();

    dim3 gout(E_ / 128, M_ / 128);
    gemm_out_mma<<<gout, 256, GEMM_SMEM>>>(out);
}